// round 16
// baseline (speedup 1.0000x reference)
#include <cuda_runtime.h>

// KAN layer, SINGLE kernel. K split by input groups (8 inputs = 72 k/chunk).
// Block (mt, ks) = 32 batch rows x all 64 outputs x inputs [ks*8, ks*8+8):
//   (a) builds its own Bs[72][64] from coef/scales (no C2t prepass),
//   (b) builds its feature sub-tile Fs[72][32] (4 nonzero cubic B-spline
//       weights + silu) from a coalesced input tile,
//   (c) 72-k loop, explicitly double-buffered (groups of 4 k): next group's
//       LDS.128-broadcast A + LDS.64 B issued before current group's packed
//       f32x2 FMAs -> forces register pipelining (breaks regs=32 serial mode),
//   (d) split-K reduce fused in epilogue (threadfence + counter, fixed ks
//       order -> bitwise deterministic; counter self-resets for graph replay).

#define IN_DIM  64
#define OUT_DIM 64
#define MAXB    2048
#define KSPLIT  8                 // chunks of 8 inputs
#define IPC     8                 // inputs per chunk
#define KCHUNK  (IPC * 9)         // 72
#define MTILE   32
#define MAXMT   (MAXB / MTILE)    // 64
#define ASTRIDE 36                // Fs row words (144B, 16B-aligned)
#define KG      4                 // k's per pipeline stage
#define NGRP    (KCHUNK / KG)     // 18

__device__ __align__(16) float g_Part[KSPLIT * MAXB * OUT_DIM];  // 4 MB
__device__ int g_cnt[MAXMT];                                     // zero-init

typedef unsigned long long ull;

__device__ __forceinline__ void ffma2(ull& d, ull a, ull b) {
    asm("fma.rn.f32x2 %0, %1, %2, %0;" : "+l"(d) : "l"(a), "l"(b));
}
__device__ __forceinline__ ull dup2(float v) {
    ull r;
    asm("mov.b64 %0, {%1, %1};" : "=l"(r) : "f"(v));
    return r;
}

__global__ __launch_bounds__(256)
void kan_gemm(const float* __restrict__ inp,
              const float* __restrict__ gridp,
              const float* __restrict__ coefp,
              const float* __restrict__ sbase,
              const float* __restrict__ ssp,
              const float* __restrict__ maskp,
              float* __restrict__ out,
              int batch)
{
    __shared__ __align__(16) float Fs[KCHUNK * ASTRIDE];   // 10.1 KB [k][b]
    __shared__ __align__(16) float Bs[KCHUNK * OUT_DIM];   // 18.0 KB [k][o]
    __shared__ float xs[MTILE][IPC + 1];                   // padded transpose
    __shared__ int s_last;

    const int mt = blockIdx.x;     // m-tile
    const int ks = blockIdx.y;     // input-group chunk
    const int b0 = mt * MTILE;
    const int i0 = ks * IPC;
    const int tid = threadIdx.x;

    // ---- input tile: 32 b x 8 i, coalesced 32B segments ----
    {
        const int b = tid >> 3;
        const int i = tid & 7;
        const int gb = b0 + b;
        xs[b][i] = (gb < batch) ? inp[gb * IN_DIM + i0 + i] : 0.0f;
    }

    // ---- Bs build straight from coef/scales: entries for (iloc, o) ----
    // Bs[(iloc*9+j)*64+o] = m*ssp*coef[s][j] (j<8) | m*sbase (j=8),
    // s = o*64 + i0 + iloc. 512 (iloc,o) pairs -> 2 per thread.
    #pragma unroll
    for (int p = 0; p < 2; ++p) {
        const int idx  = tid + 256 * p;
        const int iloc = idx >> 6;          // 0..7
        const int o    = idx & 63;
        const int s    = o * IN_DIM + i0 + iloc;
        const float4 c0 = __ldg((const float4*)coefp + s * 2);
        const float4 c1 = __ldg((const float4*)coefp + s * 2 + 1);
        const float m = maskp[s];
        const float w = m * ssp[s];
        float* brow = Bs + iloc * 9 * OUT_DIM + o;   // o = lane-ish: c-free STS
        brow[0 * OUT_DIM] = w * c0.x;
        brow[1 * OUT_DIM] = w * c0.y;
        brow[2 * OUT_DIM] = w * c0.z;
        brow[3 * OUT_DIM] = w * c0.w;
        brow[4 * OUT_DIM] = w * c1.x;
        brow[5 * OUT_DIM] = w * c1.y;
        brow[6 * OUT_DIM] = w * c1.z;
        brow[7 * OUT_DIM] = w * c1.w;
        brow[8 * OUT_DIM] = m * sbase[s];
    }
    __syncthreads();

    // ---- features: thread = (iloc = warp, bl = lane) ----
    {
        const int iloc = tid >> 5;
        const int bl   = tid & 31;
        const int i    = i0 + iloc;
        const float x  = xs[bl][iloc];

        const float g0 = __ldg(gridp + i * 6 + 0);   // warp-uniform
        const float g5 = __ldg(gridp + i * 6 + 5);
        const float h  = (g5 - g0) * 0.2f;
        const float mf = (x - (g0 - 3.0f * h)) * (1.0f / h);

        int mi = (int)floorf(mf);
        const float ok = (mi >= 0 && mi < 11) ? 1.0f : 0.0f;
        mi = max(0, min(10, mi));

        const float u  = mf - (float)mi;
        const float v  = 1.0f - u;
        const float u2 = u * u;
        const float u3 = u2 * u;
        float wg[4];
        wg[0] = ok * (v * v * v * (1.0f / 6.0f));
        wg[3] = ok * (u3 * (1.0f / 6.0f));
        wg[1] = ok * ((2.0f / 3.0f) - u2 + 0.5f * u3);
        wg[2] = ok - wg[0] - wg[1] - wg[3];

        float f[9];
        #pragma unroll
        for (int j = 0; j < 9; ++j) f[j] = 0.0f;
        #pragma unroll
        for (int r = 0; r < 4; ++r) {
            const int j = mi - 3 + r;
            if (j >= 0 && j < 8) f[j] = wg[r];
        }
        f[8] = __fdividef(x, 1.0f + __expf(-x));     // silu

        #pragma unroll
        for (int j = 0; j < 9; ++j)                  // lane-contiguous: c-free
            Fs[(iloc * 9 + j) * ASTRIDE + bl] = f[j];
    }
    __syncthreads();

    // ---- 72-k mainloop, double-buffered: thread tile 4b x 2o ----
    const int tx = tid & 31;        // o-pair base = tx*2
    const int ty = tid >> 5;        // b-quad base = ty*4

    ull acc00 = 0, acc01 = 0, acc10 = 0, acc11 = 0;  // [o][b-pair]

    const float* fsrow = Fs + ty * 4;
    const float* bsrow = Bs + tx * 2;

    ulonglong2 aC[KG], aN[KG];
    float2     bC[KG], bN[KG];

    // prime group 0
    #pragma unroll
    for (int j = 0; j < KG; ++j) {
        aC[j] = *(const ulonglong2*)(fsrow + j * ASTRIDE);
        bC[j] = *(const float2*)(bsrow + j * OUT_DIM);
    }

    #pragma unroll 2
    for (int g = 1; g < NGRP; ++g) {
        const int kb = g * KG;
        #pragma unroll
        for (int j = 0; j < KG; ++j) {       // next group's loads first
            aN[j] = *(const ulonglong2*)(fsrow + (kb + j) * ASTRIDE);
            bN[j] = *(const float2*)(bsrow + (kb + j) * OUT_DIM);
        }
        #pragma unroll
        for (int j = 0; j < KG; ++j) {       // consume current group
            const ull d0 = dup2(bC[j].x);
            const ull d1 = dup2(bC[j].y);
            ffma2(acc00, aC[j].x, d0); ffma2(acc01, aC[j].y, d0);
            ffma2(acc10, aC[j].x, d1); ffma2(acc11, aC[j].y, d1);
        }
        #pragma unroll
        for (int j = 0; j < KG; ++j) { aC[j] = aN[j]; bC[j] = bN[j]; }
    }
    #pragma unroll
    for (int j = 0; j < KG; ++j) {           // drain last group
        const ull d0 = dup2(bC[j].x);
        const ull d1 = dup2(bC[j].y);
        ffma2(acc00, aC[j].x, d0); ffma2(acc01, aC[j].y, d0);
        ffma2(acc10, aC[j].x, d1); ffma2(acc11, aC[j].y, d1);
    }

    // ---- write partial tile: float2 {o0,o0+1} per b ----
    {
        union { ull u; float2 f; } u00, u01, u10, u11;
        u00.u = acc00; u01.u = acc01;        // o0 : b+0,b+1 / b+2,b+3
        u10.u = acc10; u11.u = acc11;        // o0+1
        const float vo0[4] = { u00.f.x, u00.f.y, u01.f.x, u01.f.y };
        const float vo1[4] = { u10.f.x, u10.f.y, u11.f.x, u11.f.y };
        #pragma unroll
        for (int ib = 0; ib < 4; ++ib) {
            const int b = b0 + ty * 4 + ib;
            *(float2*)&g_Part[((ks << 11) + b) * OUT_DIM + tx * 2] =
                make_float2(vo0[ib], vo1[ib]);
        }
    }

    // ---- fused reduce: last of 8 chunk-blocks for this m-tile sums ----
    __threadfence();
    __syncthreads();
    if (tid == 0) {
        const int old = atomicAdd(&g_cnt[mt], 1);
        s_last = (old == KSPLIT - 1) ? 1 : 0;
    }
    __syncthreads();

    if (s_last) {
        __threadfence();
        const int o4 = (tid & 15) * 4;
        const int br = tid >> 4;        // 0..15
        #pragma unroll
        for (int p = 0; p < 2; ++p) {
            const int bl = br + p * 16;
            const int b  = b0 + bl;
            float4 v = make_float4(0.f, 0.f, 0.f, 0.f);
            #pragma unroll
            for (int kk = 0; kk < KSPLIT; ++kk) {
                const float4 q = *(const float4*)
                    &g_Part[((kk << 11) + b) * OUT_DIM + o4];
                v.x += q.x; v.y += q.y; v.z += q.z; v.w += q.w;
            }
            if (b < batch)
                *(float4*)&out[b * OUT_DIM + o4] = v;
        }
        if (tid == 0) g_cnt[mt] = 0;    // self-reset for graph replay
    }
}

extern "C" void kernel_launch(void* const* d_in, const int* in_sizes, int n_in,
                              void* d_out, int out_size)
{
    const float* inp   = (const float*)d_in[0];   // (batch, 64)
    const float* gridp = (const float*)d_in[1];   // (4096, 6)
    const float* coefp = (const float*)d_in[2];   // (4096, 8)
    const float* sbase = (const float*)d_in[3];   // (4096,)
    const float* ssp   = (const float*)d_in[4];   // (4096,)
    const float* maskp = (const float*)d_in[5];   // (4096,)
    float* out = (float*)d_out;                   // (batch, 64)

    int batch = in_sizes[0] / IN_DIM;
    if (batch > MAXB) batch = MAXB;

    const int mtiles = (batch + MTILE - 1) / MTILE;   // 64
    dim3 ggrid(mtiles, KSPLIT);                       // 64 x 8 = 512 blocks
    kan_gemm<<<ggrid, 256>>>(inp, gridp, coefp, sbase, ssp, maskp, out, batch);
}